// round 6
// baseline (speedup 1.0000x reference)
#include <cuda_runtime.h>
#include <cuda_fp16.h>
#include <cstdint>

// Problem dims
#define N_TOK 4096
#define KTOP  2
#define NE    8
#define DM    1024
#define DH    1024
#define NK    (N_TOK * KTOP)

#define TM    128
#define TN    128
#define KCH   64            // fp16 k per chunk (128 B row)
#define NCHUNK (DM / KCH)   // 16
#define PL    16384         // plane bytes: 128 rows * 128 B
#define MAXT  (NK / TM + NE)

#define SMEM1 (2 * 4 * PL)  // 131072 : A_hi, A_lo, W1, W3
#define SMEM2 (2 * 2 * PL)  //  65536 : A, W2

// ---------------- scratch ---------------------------------------------------
__device__ __half g_xh[(size_t)N_TOK * DM];
__device__ __half g_xl[(size_t)N_TOK * DM];
__device__ __half g_w1[(size_t)NE * DM * DH];
__device__ __half g_w3[(size_t)NE * DM * DH];
__device__ __half g_w2[(size_t)NE * DH * DM];
__device__ __half g_hh[(size_t)NK * DH];
__device__ int g_rowsrc[NK];
__device__ int g_offsets[NE];
__device__ int g_counters[NE];
__device__ int g_tile_e[MAXT];
__device__ int g_tile_r0[MAXT];
__device__ int g_tile_nrows[MAXT];
__device__ int g_ntiles;

// ---------------- helpers ---------------------------------------------------
__device__ __forceinline__ uint32_t smem_u32(const void* p) {
    uint32_t a;
    asm("{ .reg .u64 t; cvta.to.shared.u64 t, %1; cvt.u32.u64 %0, t; }"
        : "=r"(a) : "l"(p));
    return a;
}
__device__ __forceinline__ void cp16(uint32_t s, const void* g) {
    asm volatile("cp.async.cg.shared.global [%0], [%1], 16;" :: "r"(s), "l"(g));
}
#define CP_COMMIT() asm volatile("cp.async.commit_group;" ::: "memory")
#define CP_WAIT(n)  asm volatile("cp.async.wait_group %0;" :: "n"(n) : "memory")

__device__ __forceinline__ void ldm4(uint32_t* r, uint32_t a) {
    asm volatile("ldmatrix.sync.aligned.m8n8.x4.shared.b16 {%0,%1,%2,%3}, [%4];"
                 : "=r"(r[0]), "=r"(r[1]), "=r"(r[2]), "=r"(r[3]) : "r"(a));
}
__device__ __forceinline__ void mma16816(float* d, const uint32_t* a,
                                         const uint32_t* b) {
    asm volatile(
        "mma.sync.aligned.m16n8k16.row.col.f32.f16.f16.f32 "
        "{%0,%1,%2,%3}, {%4,%5,%6,%7}, {%8,%9}, {%0,%1,%2,%3};"
        : "+f"(d[0]), "+f"(d[1]), "+f"(d[2]), "+f"(d[3])
        : "r"(a[0]), "r"(a[1]), "r"(a[2]), "r"(a[3]), "r"(b[0]), "r"(b[1]));
}
__device__ __forceinline__ uint32_t swz(uint32_t off) {
    return off ^ ((off >> 3) & 0x70);
}
__device__ __forceinline__ void split_f32(float v, __half& h, __half& l) {
    h = __float2half(v);
    l = __float2half(v - __half2float(h));
}

// ---------------- setup ------------------------------------------------------
__global__ void setup_kernel(const int* __restrict__ bspe) {
    if (threadIdx.x == 0) {
        int off = 0, t = 0;
        for (int e = 0; e < NE; e++) {
            g_offsets[e] = off;
            g_counters[e] = 0;
            int cnt = bspe[e];
            for (int r = 0; r < cnt; r += TM) {
                g_tile_e[t] = e;
                g_tile_r0[t] = off + r;
                g_tile_nrows[t] = min(TM, cnt - r);
                t++;
            }
            off += cnt;
        }
        g_ntiles = t;
    }
}

// split x to fp16 hi/lo; first NK threads also do the permutation scatter
__global__ void convert_perm_kernel(const float* __restrict__ x,
                                    const int* __restrict__ idx) {
    int i = blockIdx.x * blockDim.x + threadIdx.x;
    __half h, l;
    split_f32(x[i], h, l);
    g_xh[i] = h;
    g_xl[i] = l;
    if (i < NK) {
        int e = idx[i];
        g_rowsrc[g_offsets[e] + atomicAdd(&g_counters[e], 1)] = i;
    }
}

__global__ void zero_out_kernel(float* __restrict__ out) {
    int i = blockIdx.x * blockDim.x + threadIdx.x;
    ((float4*)out)[i] = make_float4(0.f, 0.f, 0.f, 0.f);
}

// W[e][k][n] fp32 -> Wt[e][n][k] fp16. which: 0 -> fused w1&w3 (z in [0,2*NE)),
// 2 -> w2 (z in [0,NE)). 64k x 32n tiles, coalesced half2 writes.
__global__ void transpose_kernel(const float* __restrict__ Wa,
                                 const float* __restrict__ Wb, int which) {
    const float* W;
    __half* dst;
    int e;
    if (which == 0) {
        int z = blockIdx.z;
        e = z >> 1;
        if (z & 1) { W = Wb; dst = g_w3; }
        else       { W = Wa; dst = g_w1; }
    } else {
        e = blockIdx.z;
        W = Wa;
        dst = g_w2;
    }
    __shared__ float tile[64][33];
    int k0 = blockIdx.y * 64, n0 = blockIdx.x * 32;
    const float* Wp = W + (size_t)e * DM * DH;
    int tx = threadIdx.x, ty = threadIdx.y;
    #pragma unroll
    for (int j = ty; j < 64; j += 8)
        tile[j][tx] = Wp[(size_t)(k0 + j) * DH + n0 + tx];
    __syncthreads();
    size_t ob = (size_t)e * DM * DH;
    #pragma unroll
    for (int i = 0; i < 4; i++) {
        int j = ty + 8 * i;
        float v0 = tile[2 * tx][j];
        float v1 = tile[2 * tx + 1][j];
        size_t o = ob + (size_t)(n0 + j) * DM + k0 + 2 * tx;
        *(__half2*)(dst + o) = __floats2half2_rn(v0, v1);
    }
}

// ---------------- GEMM1: h = silu(x@W1) * (x@W3) ----------------------------
// planes per buf: 0=A_hi, 1=A_lo, 2=W1, 3=W3
__global__ __launch_bounds__(256, 1) void gemm1_mm() {
    int tile = blockIdx.x;
    if (tile >= g_ntiles) return;
    int e = g_tile_e[tile], row0 = g_tile_r0[tile], rows = g_tile_nrows[tile];
    int col0 = blockIdx.y * TN;
    extern __shared__ __align__(1024) char smem[];
    uint32_t sb = smem_u32(smem);
    __shared__ int toks[TM];

    int t = threadIdx.x, wid = t >> 5, l = t & 31;
    if (t < TM) {
        int tok = 0;
        if (t < rows) tok = g_rowsrc[row0 + t] / KTOP;
        toks[t] = tok;
    }
    __syncthreads();

    const __half* w1 = g_w1 + (size_t)e * DM * DH;
    const __half* w3 = g_w3 + (size_t)e * DM * DH;

    auto load_chunk = [&](int c, int buf) {
        int k0 = c * KCH;
        uint32_t base = sb + buf * 4 * PL;
        #pragma unroll
        for (int i = 0; i < 4; i++) {
            int lin = i * 256 + t, row = lin >> 3, cv = lin & 7;
            size_t ga = (size_t)toks[row] * DM + k0 + cv * 8;
            uint32_t sw = swz((uint32_t)(row * 128 + cv * 16));
            cp16(base + sw,      g_xh + ga);
            cp16(base + PL + sw, g_xl + ga);
        }
        #pragma unroll
        for (int i = 0; i < 4; i++) {
            int lin = i * 256 + t, row = lin >> 3, cv = lin & 7;
            size_t gb = (size_t)(col0 + row) * DM + k0 + cv * 8;
            uint32_t sw = swz((uint32_t)(row * 128 + cv * 16));
            cp16(base + 2 * PL + sw, w1 + gb);
            cp16(base + 3 * PL + sw, w3 + gb);
        }
        CP_COMMIT();
    };

    int m0  = (wid & 1) * 64;
    int n0w = (wid >> 1) * 32;
    float acc1[4][4][4] = {};
    float acc3[4][4][4] = {};

    load_chunk(0, 0);
    for (int c = 0; c < NCHUNK; c++) {
        int buf = c & 1;
        if (c + 1 < NCHUNK) { load_chunk(c + 1, buf ^ 1); CP_WAIT(1); }
        else                { CP_WAIT(0); }
        __syncthreads();
        uint32_t base = sb + buf * 4 * PL;
        #pragma unroll
        for (int ks = 0; ks < 4; ks++) {
            uint32_t aH[4][4], aL[4][4];
            int arow = (l & 15);
            int acol = (ks * 16 + ((l >> 4) & 1) * 8) * 2;
            #pragma unroll
            for (int mt = 0; mt < 4; mt++) {
                uint32_t off = swz((uint32_t)((m0 + mt * 16 + arow) * 128 + acol));
                ldm4(aH[mt], base + off);
                ldm4(aL[mt], base + PL + off);
            }
            int brow = (l & 7) + ((l >> 4) & 1) * 8;
            int bcol = (ks * 16 + ((l >> 3) & 1) * 8) * 2;
            #pragma unroll
            for (int np = 0; np < 2; np++) {
                uint32_t off = swz((uint32_t)((n0w + np * 16 + brow) * 128 + bcol));
                uint32_t b1[4], b3[4];
                ldm4(b1, base + 2 * PL + off);
                ldm4(b3, base + 3 * PL + off);
                #pragma unroll
                for (int mt = 0; mt < 4; mt++) {
                    #pragma unroll
                    for (int h = 0; h < 2; h++) {
                        int nt = np * 2 + h;
                        mma16816(acc1[mt][nt], aH[mt], b1 + h * 2);
                        mma16816(acc1[mt][nt], aL[mt], b1 + h * 2);
                        mma16816(acc3[mt][nt], aH[mt], b3 + h * 2);
                        mma16816(acc3[mt][nt], aL[mt], b3 + h * 2);
                    }
                }
            }
        }
        __syncthreads();
    }

    // SwiGLU epilogue -> g_hh (plain fp16 RN)
    int g = l >> 2, tg = l & 3;
    #pragma unroll
    for (int mt = 0; mt < 4; mt++) {
        #pragma unroll
        for (int half = 0; half < 2; half++) {
            int r = m0 + mt * 16 + g + half * 8;
            if (r < rows) {
                size_t rowoff = (size_t)(row0 + r) * DH + col0;
                #pragma unroll
                for (int nt = 0; nt < 4; nt++) {
                    int cc = n0w + nt * 8 + tg * 2;
                    float v0 = acc1[mt][nt][half * 2 + 0];
                    float v1 = acc1[mt][nt][half * 2 + 1];
                    float u0 = acc3[mt][nt][half * 2 + 0];
                    float u1 = acc3[mt][nt][half * 2 + 1];
                    float o0 = v0 / (1.f + __expf(-v0)) * u0;
                    float o1 = v1 / (1.f + __expf(-v1)) * u1;
                    *(__half2*)(g_hh + rowoff + cc) = __floats2half2_rn(o0, o1);
                }
            }
        }
    }
}

// ---------------- GEMM2: out[tok] += ew[c] * (h @ W2), single fp16 term -----
// planes per buf: 0=A, 1=W2
__global__ __launch_bounds__(256, 2) void gemm2_mm(const float* __restrict__ ew,
                                                   float* __restrict__ out) {
    int tile = blockIdx.x;
    if (tile >= g_ntiles) return;
    int e = g_tile_e[tile], row0 = g_tile_r0[tile], rows = g_tile_nrows[tile];
    int col0 = blockIdx.y * TN;
    extern __shared__ __align__(1024) char smem[];
    uint32_t sb = smem_u32(smem);
    __shared__ int   cpy[TM];
    __shared__ float wgt[TM];

    int t = threadIdx.x, wid = t >> 5, l = t & 31;
    if (t < TM) {
        int c = 0;
        float w = 0.f;
        if (t < rows) { c = g_rowsrc[row0 + t]; w = ew[c]; }
        cpy[t] = c;
        wgt[t] = w;
    }
    __syncthreads();

    const __half* w2 = g_w2 + (size_t)e * DH * DM;

    auto load_chunk = [&](int c, int buf) {
        int k0 = c * KCH;
        uint32_t base = sb + buf * 2 * PL;
        #pragma unroll
        for (int i = 0; i < 4; i++) {
            int lin = i * 256 + t, row = lin >> 3, cv = lin & 7;
            int rr = row0 + row;
            if (rr >= NK) rr = NK - 1;
            size_t ga = (size_t)rr * DH + k0 + cv * 8;
            uint32_t sw = swz((uint32_t)(row * 128 + cv * 16));
            cp16(base + sw, g_hh + ga);
            size_t gb = (size_t)(col0 + row) * DH + k0 + cv * 8;
            cp16(base + PL + sw, w2 + gb);
        }
        CP_COMMIT();
    };

    int m0  = (wid & 1) * 64;
    int n0w = (wid >> 1) * 32;
    float acc[4][4][4] = {};

    load_chunk(0, 0);
    for (int c = 0; c < NCHUNK; c++) {
        int buf = c & 1;
        if (c + 1 < NCHUNK) { load_chunk(c + 1, buf ^ 1); CP_WAIT(1); }
        else                { CP_WAIT(0); }
        __syncthreads();
        uint32_t base = sb + buf * 2 * PL;
        #pragma unroll
        for (int ks = 0; ks < 4; ks++) {
            uint32_t aH[4][4];
            int arow = (l & 15);
            int acol = (ks * 16 + ((l >> 4) & 1) * 8) * 2;
            #pragma unroll
            for (int mt = 0; mt < 4; mt++) {
                uint32_t off = swz((uint32_t)((m0 + mt * 16 + arow) * 128 + acol));
                ldm4(aH[mt], base + off);
            }
            int brow = (l & 7) + ((l >> 4) & 1) * 8;
            int bcol = (ks * 16 + ((l >> 3) & 1) * 8) * 2;
            #pragma unroll
            for (int np = 0; np < 2; np++) {
                uint32_t off = swz((uint32_t)((n0w + np * 16 + brow) * 128 + bcol));
                uint32_t bh[4];
                ldm4(bh, base + PL + off);
                #pragma unroll
                for (int mt = 0; mt < 4; mt++) {
                    #pragma unroll
                    for (int h = 0; h < 2; h++) {
                        int nt = np * 2 + h;
                        mma16816(acc[mt][nt], aH[mt], bh + h * 2);
                    }
                }
            }
        }
        __syncthreads();
    }

    // weighted atomic combine into out (exactly K=2 commutative fp32 adds per
    // element onto a zeroed buffer -> deterministic)
    int g = l >> 2, tg = l & 3;
    #pragma unroll
    for (int mt = 0; mt < 4; mt++) {
        #pragma unroll
        for (int half = 0; half < 2; half++) {
            int r = m0 + mt * 16 + g + half * 8;
            if (r < rows) {
                int   tok = cpy[r] / KTOP;
                float w   = wgt[r];
                float* dst = out + (size_t)tok * DM + col0;
                #pragma unroll
                for (int nt = 0; nt < 4; nt++) {
                    int cc = n0w + nt * 8 + tg * 2;
                    atomicAdd(&dst[cc],     w * acc[mt][nt][half * 2 + 0]);
                    atomicAdd(&dst[cc + 1], w * acc[mt][nt][half * 2 + 1]);
                }
            }
        }
    }
}

// ---------------- launch -----------------------------------------------------
extern "C" void kernel_launch(void* const* d_in, const int* in_sizes, int n_in,
                              void* d_out, int out_size) {
    const float* x    = (const float*)d_in[0];
    const float* ew   = (const float*)d_in[1];
    const int*   idx  = (const int*)  d_in[2];
    const int*   bspe = (const int*)  d_in[3];
    const float* w1   = (const float*)d_in[4];
    const float* w2   = (const float*)d_in[5];
    const float* w3   = (const float*)d_in[6];
    float*       out  = (float*)d_out;

    cudaFuncSetAttribute(gemm1_mm, cudaFuncAttributeMaxDynamicSharedMemorySize, SMEM1);
    cudaFuncSetAttribute(gemm2_mm, cudaFuncAttributeMaxDynamicSharedMemorySize, SMEM2);

    dim3 tgrid13(DH / 32, DM / 64, 2 * NE);
    dim3 tgrid2(DH / 32, DM / 64, NE);
    setup_kernel<<<1, 32>>>(bspe);                               // 1
    convert_perm_kernel<<<(N_TOK * DM) / 256, 256>>>(x, idx);    // 2
    transpose_kernel<<<tgrid13, dim3(32, 8)>>>(w1, w3, 0);       // 3
    gemm1_mm<<<dim3(MAXT, DH / TN), 256, SMEM1>>>();             // 4 <- profiled
    transpose_kernel<<<tgrid2, dim3(32, 8)>>>(w2, w2, 2);        // 5
    zero_out_kernel<<<(N_TOK * DM / 4) / 256, 256>>>(out);       // 6
    gemm2_mm<<<dim3(MAXT, DM / TN), 256, SMEM2>>>(ew, out);      // 7
}

// round 7
// speedup vs baseline: 1.4210x; 1.4210x over previous
#include <cuda_runtime.h>
#include <cuda_fp16.h>
#include <cstdint>

// Problem dims
#define N_TOK 4096
#define KTOP  2
#define NE    8
#define DM    1024
#define DH    1024
#define NK    (N_TOK * KTOP)

#define TM    128
#define TN    128
#define KCH   64            // fp16 k per chunk (128 B row)
#define NCHUNK (DM / KCH)   // 16
#define PL    16384         // plane bytes: 128 rows * 128 B
#define MAXT  (NK / TM + NE)

#define SMEM1 (2 * 4 * PL)  // 131072 : A_hi, A_lo, W1, W3
#define SMEM2 (2 * 2 * PL)  //  65536 : A, W2

// ---------------- scratch ---------------------------------------------------
__device__ __half g_xh[(size_t)N_TOK * DM];
__device__ __half g_xl[(size_t)N_TOK * DM];
__device__ __half g_w1[(size_t)NE * DM * DH];
__device__ __half g_w3[(size_t)NE * DM * DH];
__device__ __half g_w2[(size_t)NE * DH * DM];
__device__ __half g_hh[(size_t)NK * DH];
__device__ int g_rowsrc[NK];
__device__ int g_offsets[NE];
__device__ int g_counters[NE];
__device__ int g_tile_e[MAXT];
__device__ int g_tile_r0[MAXT];
__device__ int g_tile_nrows[MAXT];
__device__ int g_ntiles;

// ---------------- helpers ---------------------------------------------------
__device__ __forceinline__ uint32_t smem_u32(const void* p) {
    uint32_t a;
    asm("{ .reg .u64 t; cvta.to.shared.u64 t, %1; cvt.u32.u64 %0, t; }"
        : "=r"(a) : "l"(p));
    return a;
}
__device__ __forceinline__ void cp16(uint32_t s, const void* g) {
    asm volatile("cp.async.cg.shared.global [%0], [%1], 16;" :: "r"(s), "l"(g));
}
#define CP_COMMIT() asm volatile("cp.async.commit_group;" ::: "memory")
#define CP_WAIT(n)  asm volatile("cp.async.wait_group %0;" :: "n"(n) : "memory")

__device__ __forceinline__ void ldm4(uint32_t* r, uint32_t a) {
    asm volatile("ldmatrix.sync.aligned.m8n8.x4.shared.b16 {%0,%1,%2,%3}, [%4];"
                 : "=r"(r[0]), "=r"(r[1]), "=r"(r[2]), "=r"(r[3]) : "r"(a));
}
__device__ __forceinline__ void mma16816(float* d, const uint32_t* a,
                                         const uint32_t* b) {
    asm volatile(
        "mma.sync.aligned.m16n8k16.row.col.f32.f16.f16.f32 "
        "{%0,%1,%2,%3}, {%4,%5,%6,%7}, {%8,%9}, {%0,%1,%2,%3};"
        : "+f"(d[0]), "+f"(d[1]), "+f"(d[2]), "+f"(d[3])
        : "r"(a[0]), "r"(a[1]), "r"(a[2]), "r"(a[3]), "r"(b[0]), "r"(b[1]));
}
__device__ __forceinline__ uint32_t swz(uint32_t off) {
    return off ^ ((off >> 3) & 0x70);
}
__device__ __forceinline__ void split_f32(float v, __half& h, __half& l) {
    h = __float2half(v);
    l = __float2half(v - __half2float(h));
}

// ---------------- setup ------------------------------------------------------
__global__ void setup_kernel(const int* __restrict__ bspe) {
    if (threadIdx.x == 0) {
        int off = 0, t = 0;
        for (int e = 0; e < NE; e++) {
            g_offsets[e] = off;
            g_counters[e] = 0;
            int cnt = bspe[e];
            for (int r = 0; r < cnt; r += TM) {
                g_tile_e[t] = e;
                g_tile_r0[t] = off + r;
                g_tile_nrows[t] = min(TM, cnt - r);
                t++;
            }
            off += cnt;
        }
        g_ntiles = t;
    }
}

// split x to fp16 hi/lo; first NK threads also do the permutation scatter
__global__ void convert_perm_kernel(const float* __restrict__ x,
                                    const int* __restrict__ idx) {
    int i = blockIdx.x * blockDim.x + threadIdx.x;
    __half h, l;
    split_f32(x[i], h, l);
    g_xh[i] = h;
    g_xl[i] = l;
    if (i < NK) {
        int e = idx[i];
        g_rowsrc[g_offsets[e] + atomicAdd(&g_counters[e], 1)] = i;
    }
}

__global__ void zero_out_kernel(float* __restrict__ out) {
    int i = blockIdx.x * blockDim.x + threadIdx.x;
    ((float4*)out)[i] = make_float4(0.f, 0.f, 0.f, 0.f);
}

// W[e][k][n] fp32 -> Wt[e][n][k] fp16. which: 0 -> fused w1&w3 (z in [0,2*NE)),
// 2 -> w2 (z in [0,NE)). 64k x 32n tiles, coalesced half2 writes.
__global__ void transpose_kernel(const float* __restrict__ Wa,
                                 const float* __restrict__ Wb, int which) {
    const float* W;
    __half* dst;
    int e;
    if (which == 0) {
        int z = blockIdx.z;
        e = z >> 1;
        if (z & 1) { W = Wb; dst = g_w3; }
        else       { W = Wa; dst = g_w1; }
    } else {
        e = blockIdx.z;
        W = Wa;
        dst = g_w2;
    }
    __shared__ float tile[64][33];
    int k0 = blockIdx.y * 64, n0 = blockIdx.x * 32;
    const float* Wp = W + (size_t)e * DM * DH;
    int tx = threadIdx.x, ty = threadIdx.y;
    #pragma unroll
    for (int j = ty; j < 64; j += 8)
        tile[j][tx] = Wp[(size_t)(k0 + j) * DH + n0 + tx];
    __syncthreads();
    size_t ob = (size_t)e * DM * DH;
    #pragma unroll
    for (int i = 0; i < 4; i++) {
        int j = ty + 8 * i;
        float v0 = tile[2 * tx][j];
        float v1 = tile[2 * tx + 1][j];
        size_t o = ob + (size_t)(n0 + j) * DM + k0 + 2 * tx;
        *(__half2*)(dst + o) = __floats2half2_rn(v0, v1);
    }
}

// ---------------- GEMM1: h = silu(x@W1) * (x@W3) ----------------------------
// planes per buf: 0=A_hi, 1=A_lo, 2=W1, 3=W3
__global__ __launch_bounds__(256, 1) void gemm1_mm() {
    int tile = blockIdx.x;
    if (tile >= g_ntiles) return;
    int e = g_tile_e[tile], row0 = g_tile_r0[tile], rows = g_tile_nrows[tile];
    int col0 = blockIdx.y * TN;
    extern __shared__ __align__(1024) char smem[];
    uint32_t sb = smem_u32(smem);
    __shared__ int toks[TM];

    int t = threadIdx.x, wid = t >> 5, l = t & 31;
    if (t < TM) {
        int tok = 0;
        if (t < rows) tok = g_rowsrc[row0 + t] / KTOP;
        toks[t] = tok;
    }
    __syncthreads();

    const __half* w1 = g_w1 + (size_t)e * DM * DH;
    const __half* w3 = g_w3 + (size_t)e * DM * DH;

    auto load_chunk = [&](int c, int buf) {
        int k0 = c * KCH;
        uint32_t base = sb + buf * 4 * PL;
        #pragma unroll
        for (int i = 0; i < 4; i++) {
            int lin = i * 256 + t, row = lin >> 3, cv = lin & 7;
            size_t ga = (size_t)toks[row] * DM + k0 + cv * 8;
            uint32_t sw = swz((uint32_t)(row * 128 + cv * 16));
            cp16(base + sw,      g_xh + ga);
            cp16(base + PL + sw, g_xl + ga);
        }
        #pragma unroll
        for (int i = 0; i < 4; i++) {
            int lin = i * 256 + t, row = lin >> 3, cv = lin & 7;
            size_t gb = (size_t)(col0 + row) * DM + k0 + cv * 8;
            uint32_t sw = swz((uint32_t)(row * 128 + cv * 16));
            cp16(base + 2 * PL + sw, w1 + gb);
            cp16(base + 3 * PL + sw, w3 + gb);
        }
        CP_COMMIT();
    };

    int m0  = (wid & 1) * 64;
    int n0w = (wid >> 1) * 32;
    float acc1[4][4][4] = {};
    float acc3[4][4][4] = {};

    load_chunk(0, 0);
    for (int c = 0; c < NCHUNK; c++) {
        int buf = c & 1;
        if (c + 1 < NCHUNK) { load_chunk(c + 1, buf ^ 1); CP_WAIT(1); }
        else                { CP_WAIT(0); }
        __syncthreads();
        uint32_t base = sb + buf * 4 * PL;
        #pragma unroll
        for (int ks = 0; ks < 4; ks++) {
            uint32_t aH[4][4], aL[4][4];
            int arow = (l & 15);
            int acol = (ks * 16 + ((l >> 4) & 1) * 8) * 2;
            #pragma unroll
            for (int mt = 0; mt < 4; mt++) {
                uint32_t off = swz((uint32_t)((m0 + mt * 16 + arow) * 128 + acol));
                ldm4(aH[mt], base + off);
                ldm4(aL[mt], base + PL + off);
            }
            int brow = (l & 7) + ((l >> 4) & 1) * 8;
            int bcol = (ks * 16 + ((l >> 3) & 1) * 8) * 2;
            #pragma unroll
            for (int np = 0; np < 2; np++) {
                uint32_t off = swz((uint32_t)((n0w + np * 16 + brow) * 128 + bcol));
                uint32_t b1[4], b3[4];
                ldm4(b1, base + 2 * PL + off);
                ldm4(b3, base + 3 * PL + off);
                #pragma unroll
                for (int mt = 0; mt < 4; mt++) {
                    #pragma unroll
                    for (int h = 0; h < 2; h++) {
                        int nt = np * 2 + h;
                        mma16816(acc1[mt][nt], aH[mt], b1 + h * 2);
                        mma16816(acc1[mt][nt], aL[mt], b1 + h * 2);
                        mma16816(acc3[mt][nt], aH[mt], b3 + h * 2);
                        mma16816(acc3[mt][nt], aL[mt], b3 + h * 2);
                    }
                }
            }
        }
        __syncthreads();
    }

    // SwiGLU epilogue -> g_hh (plain fp16 RN)
    int g = l >> 2, tg = l & 3;
    #pragma unroll
    for (int mt = 0; mt < 4; mt++) {
        #pragma unroll
        for (int half = 0; half < 2; half++) {
            int r = m0 + mt * 16 + g + half * 8;
            if (r < rows) {
                size_t rowoff = (size_t)(row0 + r) * DH + col0;
                #pragma unroll
                for (int nt = 0; nt < 4; nt++) {
                    int cc = n0w + nt * 8 + tg * 2;
                    float v0 = acc1[mt][nt][half * 2 + 0];
                    float v1 = acc1[mt][nt][half * 2 + 1];
                    float u0 = acc3[mt][nt][half * 2 + 0];
                    float u1 = acc3[mt][nt][half * 2 + 1];
                    float o0 = v0 / (1.f + __expf(-v0)) * u0;
                    float o1 = v1 / (1.f + __expf(-v1)) * u1;
                    *(__half2*)(g_hh + rowoff + cc) = __floats2half2_rn(o0, o1);
                }
            }
        }
    }
}

// ---------------- GEMM2: out[tok] += ew[c] * (h @ W2), single fp16 term -----
// planes per buf: 0=A, 1=W2. Full register budget (no spills).
__global__ __launch_bounds__(256, 1) void gemm2_mm(const float* __restrict__ ew,
                                                   float* __restrict__ out) {
    int tile = blockIdx.x;
    if (tile >= g_ntiles) return;
    int e = g_tile_e[tile], row0 = g_tile_r0[tile], rows = g_tile_nrows[tile];
    int col0 = blockIdx.y * TN;
    extern __shared__ __align__(1024) char smem[];
    uint32_t sb = smem_u32(smem);
    __shared__ int   cpy[TM];
    __shared__ float wgt[TM];

    int t = threadIdx.x, wid = t >> 5, l = t & 31;
    if (t < TM) {
        int c = 0;
        float w = 0.f;
        if (t < rows) { c = g_rowsrc[row0 + t]; w = ew[c]; }
        cpy[t] = c;
        wgt[t] = w;
    }
    __syncthreads();

    const __half* w2 = g_w2 + (size_t)e * DH * DM;

    auto load_chunk = [&](int c, int buf) {
        int k0 = c * KCH;
        uint32_t base = sb + buf * 2 * PL;
        #pragma unroll
        for (int i = 0; i < 4; i++) {
            int lin = i * 256 + t, row = lin >> 3, cv = lin & 7;
            int rr = row0 + row;
            if (rr >= NK) rr = NK - 1;
            size_t ga = (size_t)rr * DH + k0 + cv * 8;
            uint32_t sw = swz((uint32_t)(row * 128 + cv * 16));
            cp16(base + sw, g_hh + ga);
            size_t gb = (size_t)(col0 + row) * DH + k0 + cv * 8;
            cp16(base + PL + sw, w2 + gb);
        }
        CP_COMMIT();
    };

    int m0  = (wid & 1) * 64;
    int n0w = (wid >> 1) * 32;
    float acc[4][4][4] = {};

    load_chunk(0, 0);
    for (int c = 0; c < NCHUNK; c++) {
        int buf = c & 1;
        if (c + 1 < NCHUNK) { load_chunk(c + 1, buf ^ 1); CP_WAIT(1); }
        else                { CP_WAIT(0); }
        __syncthreads();
        uint32_t base = sb + buf * 2 * PL;
        #pragma unroll
        for (int ks = 0; ks < 4; ks++) {
            uint32_t aH[4][4];
            int arow = (l & 15);
            int acol = (ks * 16 + ((l >> 4) & 1) * 8) * 2;
            #pragma unroll
            for (int mt = 0; mt < 4; mt++) {
                uint32_t off = swz((uint32_t)((m0 + mt * 16 + arow) * 128 + acol));
                ldm4(aH[mt], base + off);
            }
            int brow = (l & 7) + ((l >> 4) & 1) * 8;
            int bcol = (ks * 16 + ((l >> 3) & 1) * 8) * 2;
            #pragma unroll
            for (int np = 0; np < 2; np++) {
                uint32_t off = swz((uint32_t)((n0w + np * 16 + brow) * 128 + bcol));
                uint32_t bh[4];
                ldm4(bh, base + PL + off);
                #pragma unroll
                for (int mt = 0; mt < 4; mt++) {
                    #pragma unroll
                    for (int h = 0; h < 2; h++) {
                        int nt = np * 2 + h;
                        mma16816(acc[mt][nt], aH[mt], bh + h * 2);
                    }
                }
            }
        }
        __syncthreads();
    }

    // weighted atomic combine into out (exactly K=2 commutative fp32 adds per
    // element onto a zeroed buffer -> deterministic)
    int g = l >> 2, tg = l & 3;
    #pragma unroll
    for (int mt = 0; mt < 4; mt++) {
        #pragma unroll
        for (int half = 0; half < 2; half++) {
            int r = m0 + mt * 16 + g + half * 8;
            if (r < rows) {
                int   tok = cpy[r] / KTOP;
                float w   = wgt[r];
                float* dst = out + (size_t)tok * DM + col0;
                #pragma unroll
                for (int nt = 0; nt < 4; nt++) {
                    int cc = n0w + nt * 8 + tg * 2;
                    atomicAdd(&dst[cc],     w * acc[mt][nt][half * 2 + 0]);
                    atomicAdd(&dst[cc + 1], w * acc[mt][nt][half * 2 + 1]);
                }
            }
        }
    }
}

// ---------------- launch -----------------------------------------------------
extern "C" void kernel_launch(void* const* d_in, const int* in_sizes, int n_in,
                              void* d_out, int out_size) {
    const float* x    = (const float*)d_in[0];
    const float* ew   = (const float*)d_in[1];
    const int*   idx  = (const int*)  d_in[2];
    const int*   bspe = (const int*)  d_in[3];
    const float* w1   = (const float*)d_in[4];
    const float* w2   = (const float*)d_in[5];
    const float* w3   = (const float*)d_in[6];
    float*       out  = (float*)d_out;

    cudaFuncSetAttribute(gemm1_mm, cudaFuncAttributeMaxDynamicSharedMemorySize, SMEM1);
    cudaFuncSetAttribute(gemm2_mm, cudaFuncAttributeMaxDynamicSharedMemorySize, SMEM2);

    dim3 tgrid13(DH / 32, DM / 64, 2 * NE);
    dim3 tgrid2(DH / 32, DM / 64, NE);
    setup_kernel<<<1, 32>>>(bspe);                               // 1
    convert_perm_kernel<<<(N_TOK * DM) / 256, 256>>>(x, idx);    // 2
    transpose_kernel<<<tgrid13, dim3(32, 8)>>>(w1, w3, 0);       // 3
    gemm1_mm<<<dim3(MAXT, DH / TN), 256, SMEM1>>>();             // 4 <- profiled
    transpose_kernel<<<tgrid2, dim3(32, 8)>>>(w2, w2, 2);        // 5
    zero_out_kernel<<<(N_TOK * DM / 4) / 256, 256>>>(out);       // 6
    gemm2_mm<<<dim3(MAXT, DM / TN), 256, SMEM2>>>(ew, out);      // 7
}

// round 8
// speedup vs baseline: 1.8646x; 1.3121x over previous
#include <cuda_runtime.h>
#include <cuda_fp16.h>
#include <cstdint>

// Problem dims
#define N_TOK 4096
#define KTOP  2
#define NE    8
#define DM    1024
#define DH    1024
#define NK    (N_TOK * KTOP)

#define TM    128
#define TN    128
#define KCH   64            // fp16 k per chunk (128 B row)
#define NCHUNK (DM / KCH)   // 16
#define PL    16384         // plane bytes: 128 rows * 128 B
#define MAXT  (NK / TM + NE)

#define SMEM1 (2 * 3 * PL)  //  98304 : A, W1, W3
#define SMEM2 (2 * 2 * PL)  //  65536 : A, W2

// ---------------- scratch ---------------------------------------------------
__device__ __half g_xh[(size_t)N_TOK * DM];
__device__ __half g_w1[(size_t)NE * DM * DH];
__device__ __half g_w3[(size_t)NE * DM * DH];
__device__ __half g_w2[(size_t)NE * DH * DM];
__device__ __half g_hh[(size_t)NK * DH];
__device__ int g_rowsrc[NK];
__device__ int g_offsets[NE];
__device__ int g_counters[NE];
__device__ int g_tile_e[MAXT];
__device__ int g_tile_r0[MAXT];
__device__ int g_tile_nrows[MAXT];
__device__ int g_ntiles;

// ---------------- helpers ---------------------------------------------------
__device__ __forceinline__ uint32_t smem_u32(const void* p) {
    uint32_t a;
    asm("{ .reg .u64 t; cvta.to.shared.u64 t, %1; cvt.u32.u64 %0, t; }"
        : "=r"(a) : "l"(p));
    return a;
}
__device__ __forceinline__ void cp16(uint32_t s, const void* g) {
    asm volatile("cp.async.cg.shared.global [%0], [%1], 16;" :: "r"(s), "l"(g));
}
#define CP_COMMIT() asm volatile("cp.async.commit_group;" ::: "memory")
#define CP_WAIT(n)  asm volatile("cp.async.wait_group %0;" :: "n"(n) : "memory")

__device__ __forceinline__ void ldm4(uint32_t* r, uint32_t a) {
    asm volatile("ldmatrix.sync.aligned.m8n8.x4.shared.b16 {%0,%1,%2,%3}, [%4];"
                 : "=r"(r[0]), "=r"(r[1]), "=r"(r[2]), "=r"(r[3]) : "r"(a));
}
__device__ __forceinline__ void mma16816(float* d, const uint32_t* a,
                                         const uint32_t* b) {
    asm volatile(
        "mma.sync.aligned.m16n8k16.row.col.f32.f16.f16.f32 "
        "{%0,%1,%2,%3}, {%4,%5,%6,%7}, {%8,%9}, {%0,%1,%2,%3};"
        : "+f"(d[0]), "+f"(d[1]), "+f"(d[2]), "+f"(d[3])
        : "r"(a[0]), "r"(a[1]), "r"(a[2]), "r"(a[3]), "r"(b[0]), "r"(b[1]));
}
__device__ __forceinline__ uint32_t swz(uint32_t off) {
    return off ^ ((off >> 3) & 0x70);
}

// ---------------- setup ------------------------------------------------------
__global__ void setup_kernel(const int* __restrict__ bspe) {
    if (threadIdx.x == 0) {
        int off = 0, t = 0;
        for (int e = 0; e < NE; e++) {
            g_offsets[e] = off;
            g_counters[e] = 0;
            int cnt = bspe[e];
            for (int r = 0; r < cnt; r += TM) {
                g_tile_e[t] = e;
                g_tile_r0[t] = off + r;
                g_tile_nrows[t] = min(TM, cnt - r);
                t++;
            }
            off += cnt;
        }
        g_ntiles = t;
    }
}

// convert x to fp16 (single term); first NK threads also do permutation scatter
__global__ void convert_perm_kernel(const float* __restrict__ x,
                                    const int* __restrict__ idx) {
    int i = blockIdx.x * blockDim.x + threadIdx.x;
    int j = 2 * i;
    float2 v = ((const float2*)x)[i];
    *(__half2*)(g_xh + j) = __floats2half2_rn(v.x, v.y);
    if (i < NK) {
        int e = idx[i];
        g_rowsrc[g_offsets[e] + atomicAdd(&g_counters[e], 1)] = i;
    }
}

__global__ void zero_out_kernel(float* __restrict__ out) {
    int i = blockIdx.x * blockDim.x + threadIdx.x;
    ((float4*)out)[i] = make_float4(0.f, 0.f, 0.f, 0.f);
}

// W[e][k][n] fp32 -> Wt[e][n][k] fp16. which: 0 -> fused w1&w3 (z in [0,2*NE)),
// 2 -> w2 (z in [0,NE)). 64k x 32n tiles, coalesced half2 writes.
__global__ void transpose_kernel(const float* __restrict__ Wa,
                                 const float* __restrict__ Wb, int which) {
    const float* W;
    __half* dst;
    int e;
    if (which == 0) {
        int z = blockIdx.z;
        e = z >> 1;
        if (z & 1) { W = Wb; dst = g_w3; }
        else       { W = Wa; dst = g_w1; }
    } else {
        e = blockIdx.z;
        W = Wa;
        dst = g_w2;
    }
    __shared__ float tile[64][33];
    int k0 = blockIdx.y * 64, n0 = blockIdx.x * 32;
    const float* Wp = W + (size_t)e * DM * DH;
    int tx = threadIdx.x, ty = threadIdx.y;
    #pragma unroll
    for (int j = ty; j < 64; j += 8)
        tile[j][tx] = Wp[(size_t)(k0 + j) * DH + n0 + tx];
    __syncthreads();
    size_t ob = (size_t)e * DM * DH;
    #pragma unroll
    for (int i = 0; i < 4; i++) {
        int j = ty + 8 * i;
        float v0 = tile[2 * tx][j];
        float v1 = tile[2 * tx + 1][j];
        size_t o = ob + (size_t)(n0 + j) * DM + k0 + 2 * tx;
        *(__half2*)(dst + o) = __floats2half2_rn(v0, v1);
    }
}

// ---------------- GEMM1: h = silu(x@W1) * (x@W3), single fp16 term ----------
// planes per buf: 0=A, 1=W1, 2=W3
__global__ __launch_bounds__(256, 1) void gemm1_mm() {
    int tile = blockIdx.x;
    if (tile >= g_ntiles) return;
    int e = g_tile_e[tile], row0 = g_tile_r0[tile], rows = g_tile_nrows[tile];
    int col0 = blockIdx.y * TN;
    extern __shared__ __align__(1024) char smem[];
    uint32_t sb = smem_u32(smem);
    __shared__ int toks[TM];

    int t = threadIdx.x, wid = t >> 5, l = t & 31;
    if (t < TM) {
        int tok = 0;
        if (t < rows) tok = g_rowsrc[row0 + t] / KTOP;
        toks[t] = tok;
    }
    __syncthreads();

    const __half* w1 = g_w1 + (size_t)e * DM * DH;
    const __half* w3 = g_w3 + (size_t)e * DM * DH;

    auto load_chunk = [&](int c, int buf) {
        int k0 = c * KCH;
        uint32_t base = sb + buf * 3 * PL;
        #pragma unroll
        for (int i = 0; i < 4; i++) {
            int lin = i * 256 + t, row = lin >> 3, cv = lin & 7;
            size_t ga = (size_t)toks[row] * DM + k0 + cv * 8;
            uint32_t sw = swz((uint32_t)(row * 128 + cv * 16));
            cp16(base + sw, g_xh + ga);
            size_t gb = (size_t)(col0 + row) * DM + k0 + cv * 8;
            cp16(base + PL + sw,     w1 + gb);
            cp16(base + 2 * PL + sw, w3 + gb);
        }
        CP_COMMIT();
    };

    int m0  = (wid & 1) * 64;
    int n0w = (wid >> 1) * 32;
    float acc1[4][4][4] = {};
    float acc3[4][4][4] = {};

    load_chunk(0, 0);
    for (int c = 0; c < NCHUNK; c++) {
        int buf = c & 1;
        if (c + 1 < NCHUNK) { load_chunk(c + 1, buf ^ 1); CP_WAIT(1); }
        else                { CP_WAIT(0); }
        __syncthreads();
        uint32_t base = sb + buf * 3 * PL;
        #pragma unroll
        for (int ks = 0; ks < 4; ks++) {
            uint32_t aH[4][4];
            int arow = (l & 15);
            int acol = (ks * 16 + ((l >> 4) & 1) * 8) * 2;
            #pragma unroll
            for (int mt = 0; mt < 4; mt++) {
                uint32_t off = swz((uint32_t)((m0 + mt * 16 + arow) * 128 + acol));
                ldm4(aH[mt], base + off);
            }
            int brow = (l & 7) + ((l >> 4) & 1) * 8;
            int bcol = (ks * 16 + ((l >> 3) & 1) * 8) * 2;
            #pragma unroll
            for (int np = 0; np < 2; np++) {
                uint32_t off = swz((uint32_t)((n0w + np * 16 + brow) * 128 + bcol));
                uint32_t b1[4], b3[4];
                ldm4(b1, base + PL + off);
                ldm4(b3, base + 2 * PL + off);
                #pragma unroll
                for (int mt = 0; mt < 4; mt++) {
                    #pragma unroll
                    for (int h = 0; h < 2; h++) {
                        int nt = np * 2 + h;
                        mma16816(acc1[mt][nt], aH[mt], b1 + h * 2);
                        mma16816(acc3[mt][nt], aH[mt], b3 + h * 2);
                    }
                }
            }
        }
        __syncthreads();
    }

    // SwiGLU epilogue -> g_hh (plain fp16 RN)
    int g = l >> 2, tg = l & 3;
    #pragma unroll
    for (int mt = 0; mt < 4; mt++) {
        #pragma unroll
        for (int half = 0; half < 2; half++) {
            int r = m0 + mt * 16 + g + half * 8;
            if (r < rows) {
                size_t rowoff = (size_t)(row0 + r) * DH + col0;
                #pragma unroll
                for (int nt = 0; nt < 4; nt++) {
                    int cc = n0w + nt * 8 + tg * 2;
                    float v0 = acc1[mt][nt][half * 2 + 0];
                    float v1 = acc1[mt][nt][half * 2 + 1];
                    float u0 = acc3[mt][nt][half * 2 + 0];
                    float u1 = acc3[mt][nt][half * 2 + 1];
                    float o0 = v0 / (1.f + __expf(-v0)) * u0;
                    float o1 = v1 / (1.f + __expf(-v1)) * u1;
                    *(__half2*)(g_hh + rowoff + cc) = __floats2half2_rn(o0, o1);
                }
            }
        }
    }
}

// ---------------- GEMM2: out[tok] += ew[c] * (h @ W2), single fp16 term -----
// planes per buf: 0=A, 1=W2. Full register budget (no spills).
__global__ __launch_bounds__(256, 1) void gemm2_mm(const float* __restrict__ ew,
                                                   float* __restrict__ out) {
    int tile = blockIdx.x;
    if (tile >= g_ntiles) return;
    int e = g_tile_e[tile], row0 = g_tile_r0[tile], rows = g_tile_nrows[tile];
    int col0 = blockIdx.y * TN;
    extern __shared__ __align__(1024) char smem[];
    uint32_t sb = smem_u32(smem);
    __shared__ int   cpy[TM];
    __shared__ float wgt[TM];

    int t = threadIdx.x, wid = t >> 5, l = t & 31;
    if (t < TM) {
        int c = 0;
        float w = 0.f;
        if (t < rows) { c = g_rowsrc[row0 + t]; w = ew[c]; }
        cpy[t] = c;
        wgt[t] = w;
    }
    __syncthreads();

    const __half* w2 = g_w2 + (size_t)e * DH * DM;

    auto load_chunk = [&](int c, int buf) {
        int k0 = c * KCH;
        uint32_t base = sb + buf * 2 * PL;
        #pragma unroll
        for (int i = 0; i < 4; i++) {
            int lin = i * 256 + t, row = lin >> 3, cv = lin & 7;
            int rr = row0 + row;
            if (rr >= NK) rr = NK - 1;
            size_t ga = (size_t)rr * DH + k0 + cv * 8;
            uint32_t sw = swz((uint32_t)(row * 128 + cv * 16));
            cp16(base + sw, g_hh + ga);
            size_t gb = (size_t)(col0 + row) * DH + k0 + cv * 8;
            cp16(base + PL + sw, w2 + gb);
        }
        CP_COMMIT();
    };

    int m0  = (wid & 1) * 64;
    int n0w = (wid >> 1) * 32;
    float acc[4][4][4] = {};

    load_chunk(0, 0);
    for (int c = 0; c < NCHUNK; c++) {
        int buf = c & 1;
        if (c + 1 < NCHUNK) { load_chunk(c + 1, buf ^ 1); CP_WAIT(1); }
        else                { CP_WAIT(0); }
        __syncthreads();
        uint32_t base = sb + buf * 2 * PL;
        #pragma unroll
        for (int ks = 0; ks < 4; ks++) {
            uint32_t aH[4][4];
            int arow = (l & 15);
            int acol = (ks * 16 + ((l >> 4) & 1) * 8) * 2;
            #pragma unroll
            for (int mt = 0; mt < 4; mt++) {
                uint32_t off = swz((uint32_t)((m0 + mt * 16 + arow) * 128 + acol));
                ldm4(aH[mt], base + off);
            }
            int brow = (l & 7) + ((l >> 4) & 1) * 8;
            int bcol = (ks * 16 + ((l >> 3) & 1) * 8) * 2;
            #pragma unroll
            for (int np = 0; np < 2; np++) {
                uint32_t off = swz((uint32_t)((n0w + np * 16 + brow) * 128 + bcol));
                uint32_t bh[4];
                ldm4(bh, base + PL + off);
                #pragma unroll
                for (int mt = 0; mt < 4; mt++) {
                    #pragma unroll
                    for (int h = 0; h < 2; h++) {
                        int nt = np * 2 + h;
                        mma16816(acc[mt][nt], aH[mt], bh + h * 2);
                    }
                }
            }
        }
        __syncthreads();
    }

    // weighted atomic combine into out (exactly K=2 commutative fp32 adds per
    // element onto a zeroed buffer -> deterministic)
    int g = l >> 2, tg = l & 3;
    #pragma unroll
    for (int mt = 0; mt < 4; mt++) {
        #pragma unroll
        for (int half = 0; half < 2; half++) {
            int r = m0 + mt * 16 + g + half * 8;
            if (r < rows) {
                int   tok = cpy[r] / KTOP;
                float w   = wgt[r];
                float* dst = out + (size_t)tok * DM + col0;
                #pragma unroll
                for (int nt = 0; nt < 4; nt++) {
                    int cc = n0w + nt * 8 + tg * 2;
                    atomicAdd(&dst[cc],     w * acc[mt][nt][half * 2 + 0]);
                    atomicAdd(&dst[cc + 1], w * acc[mt][nt][half * 2 + 1]);
                }
            }
        }
    }
}

// ---------------- launch -----------------------------------------------------
extern "C" void kernel_launch(void* const* d_in, const int* in_sizes, int n_in,
                              void* d_out, int out_size) {
    const float* x    = (const float*)d_in[0];
    const float* ew   = (const float*)d_in[1];
    const int*   idx  = (const int*)  d_in[2];
    const int*   bspe = (const int*)  d_in[3];
    const float* w1   = (const float*)d_in[4];
    const float* w2   = (const float*)d_in[5];
    const float* w3   = (const float*)d_in[6];
    float*       out  = (float*)d_out;

    cudaFuncSetAttribute(gemm1_mm, cudaFuncAttributeMaxDynamicSharedMemorySize, SMEM1);
    cudaFuncSetAttribute(gemm2_mm, cudaFuncAttributeMaxDynamicSharedMemorySize, SMEM2);

    dim3 tgrid13(DH / 32, DM / 64, 2 * NE);
    dim3 tgrid2(DH / 32, DM / 64, NE);
    setup_kernel<<<1, 32>>>(bspe);                               // 1
    convert_perm_kernel<<<(N_TOK * DM / 2) / 256, 256>>>(x, idx);// 2
    transpose_kernel<<<tgrid13, dim3(32, 8)>>>(w1, w3, 0);       // 3
    gemm1_mm<<<dim3(MAXT, DH / TN), 256, SMEM1>>>();             // 4 <- profiled
    transpose_kernel<<<tgrid2, dim3(32, 8)>>>(w2, w2, 2);        // 5
    zero_out_kernel<<<(N_TOK * DM / 4) / 256, 256>>>(out);       // 6
    gemm2_mm<<<dim3(MAXT, DM / TN), 256, SMEM2>>>(ew, out);      // 7
}